// round 2
// baseline (speedup 1.0000x reference)
#include <cuda_runtime.h>
#include <cuda_bf16.h>

#define N_NODES 50000
#define N_EDGES 800000
#define N_GRAPHS 1024

// Scratch (device globals: allocation-free rule)
__device__ float g_aggr[(size_t)N_NODES * 512];
__device__ float g_h1[(size_t)N_NODES * 256];
__device__ float g_h2[(size_t)N_NODES * 512];
__device__ float g_h3[(size_t)N_NODES * 512];

// ---------------------------------------------------------------------------
// Zero kernel (float4 grid-stride)
// ---------------------------------------------------------------------------
__global__ void zero_kernel(float4* __restrict__ p, int n4) {
    int i = blockIdx.x * blockDim.x + threadIdx.x;
    int stride = gridDim.x * blockDim.x;
    float4 z = make_float4(0.f, 0.f, 0.f, 0.f);
    for (; i < n4; i += stride) p[i] = z;
}

// ---------------------------------------------------------------------------
// Edge scatter: aggr[dst] += x[src].  Warp per edge.
// d = 78 variant uses float2 vector reductions (39 chunks).
// Indices are int32 (JAX x64 disabled: jnp.int64 -> int32 on device).
// ---------------------------------------------------------------------------
__global__ void scatter78(const float* __restrict__ x,
                          const int* __restrict__ ei,
                          float* __restrict__ aggr) {
    int e = (blockIdx.x * blockDim.x + threadIdx.x) >> 5;
    int lane = threadIdx.x & 31;
    if (e >= N_EDGES) return;
    int s = ei[e];
    int t = ei[N_EDGES + e];
    const float2* xs = (const float2*)(x + (size_t)s * 78);
    float2* ad = (float2*)(aggr + (size_t)t * 78);
    #pragma unroll 2
    for (int c = lane; c < 39; c += 32) {
        float2 v = xs[c];
        asm volatile("red.global.add.v2.f32 [%0], {%1, %2};"
                     :: "l"(ad + c), "f"(v.x), "f"(v.y) : "memory");
    }
}

// d divisible by 4 variant (d = 256 or 512): float4 vector reductions.
__global__ void scatter_vec4(const float* __restrict__ x,
                             const int* __restrict__ ei,
                             float* __restrict__ aggr, int d) {
    int e = (blockIdx.x * blockDim.x + threadIdx.x) >> 5;
    int lane = threadIdx.x & 31;
    if (e >= N_EDGES) return;
    int s = ei[e];
    int t = ei[N_EDGES + e];
    int d4 = d >> 2;
    const float4* xs = (const float4*)(x + (size_t)s * d);
    float4* ad = (float4*)(aggr + (size_t)t * d);
    for (int c = lane; c < d4; c += 32) {
        float4 v = xs[c];
        asm volatile("red.global.add.v4.f32 [%0], {%1, %2, %3, %4};"
                     :: "l"(ad + c), "f"(v.x), "f"(v.y), "f"(v.z), "f"(v.w)
                     : "memory");
    }
}

// ---------------------------------------------------------------------------
// Dual GEMM + bias + ReLU:  C = relu(A1 @ B1 + A2 @ B2 + bias)
// A1, A2: [N, K] row-major.  B1, B2: [K, M] row-major.  C: [N, M].
// Tile 128x128, BK=8, 256 threads, each computes 8x8.
// ---------------------------------------------------------------------------
#define BM 128
#define BN 128
#define BK 8
#define TM 8
#define TN 8

__global__ __launch_bounds__(256)
void dual_gemm_relu(const float* __restrict__ A1, const float* __restrict__ B1,
                    const float* __restrict__ A2, const float* __restrict__ B2,
                    const float* __restrict__ bias, float* __restrict__ C,
                    int N, int K, int M) {
    __shared__ float As[BK][BM];
    __shared__ float Bs[BK][BN];

    int tid = threadIdx.x;
    int tx = tid % (BN / TN);       // 0..15 (col group)
    int ty = tid / (BN / TN);       // 0..15 (row group)
    int rowBase = blockIdx.y * BM;
    int colBase = blockIdx.x * BN;

    float acc[TM][TN];
    #pragma unroll
    for (int i = 0; i < TM; i++)
        #pragma unroll
        for (int j = 0; j < TN; j++) acc[i][j] = 0.f;

    #pragma unroll 1
    for (int pass = 0; pass < 2; ++pass) {
        const float* A = pass ? A2 : A1;
        const float* B = pass ? B2 : B1;
        for (int k0 = 0; k0 < K; k0 += BK) {
            // Load A tile (BM x BK)
            #pragma unroll
            for (int i = 0; i < (BM * BK) / 256; ++i) {
                int e = tid + i * 256;
                int m = e / BK, kk = e % BK;
                int gr = rowBase + m, gk = k0 + kk;
                As[kk][m] = (gr < N && gk < K) ? A[(size_t)gr * K + gk] : 0.f;
            }
            // Load B tile (BK x BN)
            #pragma unroll
            for (int i = 0; i < (BK * BN) / 256; ++i) {
                int e = tid + i * 256;
                int kk = e / BN, n = e % BN;
                int gk = k0 + kk, gc = colBase + n;
                Bs[kk][n] = (gk < K && gc < M) ? B[(size_t)gk * M + gc] : 0.f;
            }
            __syncthreads();
            #pragma unroll
            for (int kk = 0; kk < BK; ++kk) {
                float ra[TM], rb[TN];
                #pragma unroll
                for (int i = 0; i < TM; i++) ra[i] = As[kk][ty * TM + i];
                #pragma unroll
                for (int j = 0; j < TN; j++) rb[j] = Bs[kk][tx * TN + j];
                #pragma unroll
                for (int i = 0; i < TM; i++)
                    #pragma unroll
                    for (int j = 0; j < TN; j++)
                        acc[i][j] += ra[i] * rb[j];
            }
            __syncthreads();
        }
    }

    // Epilogue: bias + ReLU
    #pragma unroll
    for (int i = 0; i < TM; i++) {
        int gr = rowBase + ty * TM + i;
        if (gr >= N) continue;
        #pragma unroll
        for (int j = 0; j < TN; j++) {
            int gc = colBase + tx * TN + j;
            if (gc >= M) continue;
            float v = acc[i][j] + bias[gc];
            C[(size_t)gr * M + gc] = v > 0.f ? v : 0.f;
        }
    }
}

// ---------------------------------------------------------------------------
// FC (512->128) + LayerNorm(128) + ReLU + graph pooling (segment_sum, sorted
// batch).  Block = 128 threads (one per output column), FC_ROWS rows/block.
// ---------------------------------------------------------------------------
#define FC_ROWS 16

__global__ __launch_bounds__(128)
void fc_ln_pool(const float* __restrict__ h, const float* __restrict__ W,
                const float* __restrict__ bfc, const float* __restrict__ lng,
                const float* __restrict__ lnb,
                const int* __restrict__ batch,
                float* __restrict__ xa, float* __restrict__ pooled, int N) {
    __shared__ float sh[FC_ROWS][512];
    __shared__ float ws[4], ws2[4];

    int c = threadIdx.x;            // column 0..127
    int lane = c & 31;
    int wid = c >> 5;
    int r0 = blockIdx.x * FC_ROWS;
    int nr = min(FC_ROWS, N - r0);

    // Stage rows into smem
    for (int r = 0; r < nr; ++r) {
        const float4* src = (const float4*)(h + (size_t)(r0 + r) * 512);
        ((float4*)sh[r])[c] = src[c];
    }
    __syncthreads();

    // Dense 512->128: acc[r] = dot(h[r0+r], W[:, c])
    float acc[FC_ROWS];
    #pragma unroll
    for (int r = 0; r < FC_ROWS; r++) acc[r] = 0.f;

    #pragma unroll 4
    for (int k = 0; k < 512; ++k) {
        float w = W[(size_t)k * 128 + c];
        #pragma unroll
        for (int r = 0; r < FC_ROWS; r++) acc[r] += sh[r][k] * w;
    }

    // Per-row LayerNorm + ReLU + pooling
    float pacc = 0.f;
    int curg = -1;
    for (int r = 0; r < nr; ++r) {
        float v = acc[r] + bfc[c];
        float s = v, s2 = v * v;
        #pragma unroll
        for (int o = 16; o > 0; o >>= 1) {
            s  += __shfl_xor_sync(0xffffffffu, s, o);
            s2 += __shfl_xor_sync(0xffffffffu, s2, o);
        }
        __syncthreads();
        if (lane == 0) { ws[wid] = s; ws2[wid] = s2; }
        __syncthreads();
        float sum = ws[0] + ws[1] + ws[2] + ws[3];
        float sum2 = ws2[0] + ws2[1] + ws2[2] + ws2[3];
        float mu = sum * (1.f / 128.f);
        float var = sum2 * (1.f / 128.f) - mu * mu;
        float z = (v - mu) * rsqrtf(var + 1e-5f) * lng[c] + lnb[c];
        float relu = z > 0.f ? z : 0.f;
        xa[(size_t)(r0 + r) * 128 + c] = relu;

        int g = batch[r0 + r];
        if (g != curg) {
            if (curg >= 0) atomicAdd(&pooled[(size_t)curg * 128 + c], pacc);
            curg = g;
            pacc = 0.f;
        }
        pacc += relu;
    }
    if (curg >= 0) atomicAdd(&pooled[(size_t)curg * 128 + c], pacc);
}

// ---------------------------------------------------------------------------
// Launch
// ---------------------------------------------------------------------------
extern "C" void kernel_launch(void* const* d_in, const int* in_sizes, int n_in,
                              void* d_out, int out_size) {
    const float* x     = (const float*)d_in[0];
    const int*   ei    = (const int*)d_in[1];
    const int*   batch = (const int*)d_in[2];
    const float* W1r = (const float*)d_in[3];
    const float* b1  = (const float*)d_in[4];
    const float* W1o = (const float*)d_in[5];
    const float* W2r = (const float*)d_in[6];
    const float* b2  = (const float*)d_in[7];
    const float* W2o = (const float*)d_in[8];
    const float* W3r = (const float*)d_in[9];
    const float* b3  = (const float*)d_in[10];
    const float* W3o = (const float*)d_in[11];
    const float* Wfc = (const float*)d_in[12];
    const float* bfc = (const float*)d_in[13];
    const float* lng = (const float*)d_in[14];
    const float* lnb = (const float*)d_in[15];

    float* out = (float*)d_out;
    float* x_atom = out;
    float* pooled = out + (size_t)N_NODES * 128;

    float *aggr, *h1, *h2, *h3;
    cudaGetSymbolAddress((void**)&aggr, g_aggr);
    cudaGetSymbolAddress((void**)&h1, g_h1);
    cudaGetSymbolAddress((void**)&h2, g_h2);
    cudaGetSymbolAddress((void**)&h3, g_h3);

    const int scatterBlocks = (N_EDGES * 32 + 255) / 256;  // warp per edge

    // ---- Layer 1: 78 -> 256 ----
    zero_kernel<<<2048, 256>>>((float4*)aggr, N_NODES * 78 / 4);
    scatter78<<<scatterBlocks, 256>>>(x, ei, aggr);
    {
        dim3 grid(256 / BN, (N_NODES + BM - 1) / BM);
        dual_gemm_relu<<<grid, 256>>>(aggr, W1r, x, W1o, b1, h1,
                                      N_NODES, 78, 256);
    }

    // ---- Layer 2: 256 -> 512 ----
    zero_kernel<<<2048, 256>>>((float4*)aggr, N_NODES * 256 / 4);
    scatter_vec4<<<scatterBlocks, 256>>>(h1, ei, aggr, 256);
    {
        dim3 grid(512 / BN, (N_NODES + BM - 1) / BM);
        dual_gemm_relu<<<grid, 256>>>(aggr, W2r, h1, W2o, b2, h2,
                                      N_NODES, 256, 512);
    }

    // ---- Layer 3: 512 -> 512 ----
    zero_kernel<<<2048, 256>>>((float4*)aggr, N_NODES * 512 / 4);
    scatter_vec4<<<scatterBlocks, 256>>>(h2, ei, aggr, 512);
    {
        dim3 grid(512 / BN, (N_NODES + BM - 1) / BM);
        dual_gemm_relu<<<grid, 256>>>(aggr, W3r, h2, W3o, b3, h3,
                                      N_NODES, 512, 512);
    }

    // ---- FC + LayerNorm + ReLU + pooling ----
    zero_kernel<<<128, 256>>>((float4*)pooled, N_GRAPHS * 128 / 4);
    fc_ln_pool<<<(N_NODES + FC_ROWS - 1) / FC_ROWS, 128>>>(
        h3, Wfc, bfc, lng, lnb, batch, x_atom, pooled, N_NODES);
}

// round 3
// speedup vs baseline: 1.1799x; 1.1799x over previous
#include <cuda_runtime.h>
#include <cuda_bf16.h>

#define N_NODES 50000
#define N_EDGES 800000
#define N_GRAPHS 1024

// Scratch (device globals: allocation-free rule)
__device__ float g_aggr[(size_t)N_NODES * 512];
__device__ float g_h1[(size_t)N_NODES * 256];
__device__ float g_h2[(size_t)N_NODES * 512];
__device__ float g_h3[(size_t)N_NODES * 512];

// ---------------------------------------------------------------------------
// Zero kernel (float4 grid-stride)
// ---------------------------------------------------------------------------
__global__ void zero_kernel(float4* __restrict__ p, int n4) {
    int i = blockIdx.x * blockDim.x + threadIdx.x;
    int stride = gridDim.x * blockDim.x;
    float4 z = make_float4(0.f, 0.f, 0.f, 0.f);
    for (; i < n4; i += stride) p[i] = z;
}

// ---------------------------------------------------------------------------
// Edge scatter: aggr[dst] += x[src].  Warp per edge.  int32 indices.
// ---------------------------------------------------------------------------
__global__ void scatter78(const float* __restrict__ x,
                          const int* __restrict__ ei,
                          float* __restrict__ aggr) {
    int e = (blockIdx.x * blockDim.x + threadIdx.x) >> 5;
    int lane = threadIdx.x & 31;
    if (e >= N_EDGES) return;
    int s = ei[e];
    int t = ei[N_EDGES + e];
    const float2* xs = (const float2*)(x + (size_t)s * 78);
    float2* ad = (float2*)(aggr + (size_t)t * 78);
    #pragma unroll 2
    for (int c = lane; c < 39; c += 32) {
        float2 v = xs[c];
        asm volatile("red.global.add.v2.f32 [%0], {%1, %2};"
                     :: "l"(ad + c), "f"(v.x), "f"(v.y) : "memory");
    }
}

__global__ void scatter_vec4(const float* __restrict__ x,
                             const int* __restrict__ ei,
                             float* __restrict__ aggr, int d) {
    int e = (blockIdx.x * blockDim.x + threadIdx.x) >> 5;
    int lane = threadIdx.x & 31;
    if (e >= N_EDGES) return;
    int s = ei[e];
    int t = ei[N_EDGES + e];
    int d4 = d >> 2;
    const float4* xs = (const float4*)(x + (size_t)s * d);
    float4* ad = (float4*)(aggr + (size_t)t * d);
    for (int c = lane; c < d4; c += 32) {
        float4 v = xs[c];
        asm volatile("red.global.add.v4.f32 [%0], {%1, %2, %3, %4};"
                     :: "l"(ad + c), "f"(v.x), "f"(v.y), "f"(v.z), "f"(v.w)
                     : "memory");
    }
}

// ---------------------------------------------------------------------------
// Dual GEMM (3xTF32 via mma.sync) + bias + ReLU:
//   C = relu(A1 @ B1 + A2 @ B2 + bias)
// A: [N, K] fp32 row-major.  B: [K, M] fp32 row-major.  C: [N, M].
// CTA tile 128x128, BK=16, 8 warps of 32x64.  Each fp32 operand is split into
// tf32 hi + lo; products hh + lh + hl accumulated in fp32 (fp32-grade error).
// ---------------------------------------------------------------------------
#define BM 128
#define BN 128
#define BKT 16
#define APAD 4
#define BPAD 4

__device__ __forceinline__ unsigned f2tf32(float v) {
    unsigned u;
    asm("cvt.rna.tf32.f32 %0, %1;" : "=r"(u) : "f"(v));
    return u;
}

__device__ __forceinline__ void mma_tf32(float* c, const unsigned* a,
                                         unsigned b0, unsigned b1) {
    asm volatile(
        "mma.sync.aligned.m16n8k8.row.col.f32.tf32.tf32.f32 "
        "{%0,%1,%2,%3}, {%4,%5,%6,%7}, {%8,%9}, {%0,%1,%2,%3};"
        : "+f"(c[0]), "+f"(c[1]), "+f"(c[2]), "+f"(c[3])
        : "r"(a[0]), "r"(a[1]), "r"(a[2]), "r"(a[3]), "r"(b0), "r"(b1));
}

__global__ __launch_bounds__(256, 1)
void dual_gemm_tf32(const float* __restrict__ A1, const float* __restrict__ B1,
                    const float* __restrict__ A2, const float* __restrict__ B2,
                    const float* __restrict__ bias, float* __restrict__ C,
                    int N, int K, int M) {
    __shared__ float Ah[BM][BKT + APAD];
    __shared__ float Al[BM][BKT + APAD];
    __shared__ float Bh[BKT][BN + BPAD];
    __shared__ float Bl[BKT][BN + BPAD];

    int tid = threadIdx.x;
    int lane = tid & 31, wid = tid >> 5;
    int wr = wid & 3, wc = wid >> 2;   // 4x2 warp grid
    int m0w = wr * 32, n0w = wc * 64;
    int gid = lane >> 2, tig = lane & 3;

    int rowBase = blockIdx.y * BM;
    int colBase = blockIdx.x * BN;

    float acc[2][8][4];
    #pragma unroll
    for (int mt = 0; mt < 2; mt++)
        #pragma unroll
        for (int nt = 0; nt < 8; nt++)
            #pragma unroll
            for (int i = 0; i < 4; i++) acc[mt][nt][i] = 0.f;

    #pragma unroll 1
    for (int pass = 0; pass < 2; ++pass) {
        const float* A = pass ? A2 : A1;
        const float* B = pass ? B2 : B1;
        #pragma unroll 1
        for (int k0 = 0; k0 < K; k0 += BKT) {
            // Load + split A tile (BM x BKT): 8 scalars per thread
            #pragma unroll
            for (int i = 0; i < 8; ++i) {
                int idx = tid + i * 256;
                int m = idx >> 4, kk = idx & 15;
                int gr = rowBase + m, gk = k0 + kk;
                float v = (gr < N && gk < K) ? __ldg(A + (size_t)gr * K + gk) : 0.f;
                float hf = __uint_as_float(f2tf32(v));
                Ah[m][kk] = hf;
                Al[m][kk] = __uint_as_float(f2tf32(v - hf));
            }
            // Load + split B tile (BKT x BN)
            #pragma unroll
            for (int i = 0; i < 8; ++i) {
                int idx = tid + i * 256;
                int kk = idx >> 7, n = idx & 127;
                int gk = k0 + kk;
                float v = (gk < K) ? __ldg(B + (size_t)gk * M + colBase + n) : 0.f;
                float hf = __uint_as_float(f2tf32(v));
                Bh[kk][n] = hf;
                Bl[kk][n] = __uint_as_float(f2tf32(v - hf));
            }
            __syncthreads();

            #pragma unroll
            for (int ks = 0; ks < 2; ++ks) {
                int kk0 = ks * 8;
                unsigned ah[2][4], al[2][4];
                #pragma unroll
                for (int mt = 0; mt < 2; mt++) {
                    int r = m0w + mt * 16 + gid;
                    ah[mt][0] = __float_as_uint(Ah[r][kk0 + tig]);
                    ah[mt][1] = __float_as_uint(Ah[r + 8][kk0 + tig]);
                    ah[mt][2] = __float_as_uint(Ah[r][kk0 + tig + 4]);
                    ah[mt][3] = __float_as_uint(Ah[r + 8][kk0 + tig + 4]);
                    al[mt][0] = __float_as_uint(Al[r][kk0 + tig]);
                    al[mt][1] = __float_as_uint(Al[r + 8][kk0 + tig]);
                    al[mt][2] = __float_as_uint(Al[r][kk0 + tig + 4]);
                    al[mt][3] = __float_as_uint(Al[r + 8][kk0 + tig + 4]);
                }
                #pragma unroll
                for (int nt = 0; nt < 8; nt++) {
                    int c = n0w + nt * 8 + gid;
                    unsigned bh0 = __float_as_uint(Bh[kk0 + tig][c]);
                    unsigned bh1 = __float_as_uint(Bh[kk0 + tig + 4][c]);
                    unsigned bl0 = __float_as_uint(Bl[kk0 + tig][c]);
                    unsigned bl1 = __float_as_uint(Bl[kk0 + tig + 4][c]);
                    #pragma unroll
                    for (int mt = 0; mt < 2; mt++) {
                        mma_tf32(acc[mt][nt], ah[mt], bh0, bh1);
                        mma_tf32(acc[mt][nt], al[mt], bh0, bh1);
                        mma_tf32(acc[mt][nt], ah[mt], bl0, bl1);
                    }
                }
            }
            __syncthreads();
        }
    }

    // Epilogue: bias + ReLU
    #pragma unroll
    for (int mt = 0; mt < 2; mt++) {
        #pragma unroll
        for (int nt = 0; nt < 8; nt++) {
            int r = rowBase + m0w + mt * 16 + gid;
            int c = colBase + n0w + nt * 8 + tig * 2;
            float b0v = bias[c], b1v = bias[c + 1];
            if (r < N) {
                float v0 = acc[mt][nt][0] + b0v;
                float v1 = acc[mt][nt][1] + b1v;
                C[(size_t)r * M + c]     = v0 > 0.f ? v0 : 0.f;
                C[(size_t)r * M + c + 1] = v1 > 0.f ? v1 : 0.f;
            }
            int r2 = r + 8;
            if (r2 < N) {
                float v2 = acc[mt][nt][2] + b0v;
                float v3 = acc[mt][nt][3] + b1v;
                C[(size_t)r2 * M + c]     = v2 > 0.f ? v2 : 0.f;
                C[(size_t)r2 * M + c + 1] = v3 > 0.f ? v3 : 0.f;
            }
        }
    }
}

// ---------------------------------------------------------------------------
// FC (512->128) + LayerNorm(128) + ReLU + graph pooling (sorted batch).
// ---------------------------------------------------------------------------
#define FC_ROWS 16

__global__ __launch_bounds__(128)
void fc_ln_pool(const float* __restrict__ h, const float* __restrict__ W,
                const float* __restrict__ bfc, const float* __restrict__ lng,
                const float* __restrict__ lnb,
                const int* __restrict__ batch,
                float* __restrict__ xa, float* __restrict__ pooled, int N) {
    __shared__ float sh[FC_ROWS][512];
    __shared__ float ws[4], ws2[4];

    int c = threadIdx.x;
    int lane = c & 31;
    int wid = c >> 5;
    int r0 = blockIdx.x * FC_ROWS;
    int nr = min(FC_ROWS, N - r0);

    for (int r = 0; r < nr; ++r) {
        const float4* src = (const float4*)(h + (size_t)(r0 + r) * 512);
        ((float4*)sh[r])[c] = src[c];
    }
    __syncthreads();

    float acc[FC_ROWS];
    #pragma unroll
    for (int r = 0; r < FC_ROWS; r++) acc[r] = 0.f;

    #pragma unroll 4
    for (int k = 0; k < 512; ++k) {
        float w = W[(size_t)k * 128 + c];
        #pragma unroll
        for (int r = 0; r < FC_ROWS; r++) acc[r] += sh[r][k] * w;
    }

    float pacc = 0.f;
    int curg = -1;
    for (int r = 0; r < nr; ++r) {
        float v = acc[r] + bfc[c];
        float s = v, s2 = v * v;
        #pragma unroll
        for (int o = 16; o > 0; o >>= 1) {
            s  += __shfl_xor_sync(0xffffffffu, s, o);
            s2 += __shfl_xor_sync(0xffffffffu, s2, o);
        }
        __syncthreads();
        if (lane == 0) { ws[wid] = s; ws2[wid] = s2; }
        __syncthreads();
        float sum = ws[0] + ws[1] + ws[2] + ws[3];
        float sum2 = ws2[0] + ws2[1] + ws2[2] + ws2[3];
        float mu = sum * (1.f / 128.f);
        float var = sum2 * (1.f / 128.f) - mu * mu;
        float z = (v - mu) * rsqrtf(var + 1e-5f) * lng[c] + lnb[c];
        float relu = z > 0.f ? z : 0.f;
        xa[(size_t)(r0 + r) * 128 + c] = relu;

        int g = batch[r0 + r];
        if (g != curg) {
            if (curg >= 0) atomicAdd(&pooled[(size_t)curg * 128 + c], pacc);
            curg = g;
            pacc = 0.f;
        }
        pacc += relu;
    }
    if (curg >= 0) atomicAdd(&pooled[(size_t)curg * 128 + c], pacc);
}

// ---------------------------------------------------------------------------
// Launch
// ---------------------------------------------------------------------------
extern "C" void kernel_launch(void* const* d_in, const int* in_sizes, int n_in,
                              void* d_out, int out_size) {
    const float* x     = (const float*)d_in[0];
    const int*   ei    = (const int*)d_in[1];
    const int*   batch = (const int*)d_in[2];
    const float* W1r = (const float*)d_in[3];
    const float* b1  = (const float*)d_in[4];
    const float* W1o = (const float*)d_in[5];
    const float* W2r = (const float*)d_in[6];
    const float* b2  = (const float*)d_in[7];
    const float* W2o = (const float*)d_in[8];
    const float* W3r = (const float*)d_in[9];
    const float* b3  = (const float*)d_in[10];
    const float* W3o = (const float*)d_in[11];
    const float* Wfc = (const float*)d_in[12];
    const float* bfc = (const float*)d_in[13];
    const float* lng = (const float*)d_in[14];
    const float* lnb = (const float*)d_in[15];

    float* out = (float*)d_out;
    float* x_atom = out;
    float* pooled = out + (size_t)N_NODES * 128;

    float *aggr, *h1, *h2, *h3;
    cudaGetSymbolAddress((void**)&aggr, g_aggr);
    cudaGetSymbolAddress((void**)&h1, g_h1);
    cudaGetSymbolAddress((void**)&h2, g_h2);
    cudaGetSymbolAddress((void**)&h3, g_h3);

    const int scatterBlocks = (N_EDGES * 32 + 255) / 256;  // warp per edge
    const int gridY = (N_NODES + BM - 1) / BM;

    // ---- Layer 1: 78 -> 256 ----
    zero_kernel<<<2048, 256>>>((float4*)aggr, N_NODES * 78 / 4);
    scatter78<<<scatterBlocks, 256>>>(x, ei, aggr);
    {
        dim3 grid(256 / BN, gridY);
        dual_gemm_tf32<<<grid, 256>>>(aggr, W1r, x, W1o, b1, h1,
                                      N_NODES, 78, 256);
    }

    // ---- Layer 2: 256 -> 512 ----
    zero_kernel<<<2048, 256>>>((float4*)aggr, N_NODES * 256 / 4);
    scatter_vec4<<<scatterBlocks, 256>>>(h1, ei, aggr, 256);
    {
        dim3 grid(512 / BN, gridY);
        dual_gemm_tf32<<<grid, 256>>>(aggr, W2r, h1, W2o, b2, h2,
                                      N_NODES, 256, 512);
    }

    // ---- Layer 3: 512 -> 512 ----
    zero_kernel<<<2048, 256>>>((float4*)aggr, N_NODES * 512 / 4);
    scatter_vec4<<<scatterBlocks, 256>>>(h2, ei, aggr, 512);
    {
        dim3 grid(512 / BN, gridY);
        dual_gemm_tf32<<<grid, 256>>>(aggr, W3r, h2, W3o, b3, h3,
                                      N_NODES, 512, 512);
    }

    // ---- FC + LayerNorm + ReLU + pooling ----
    zero_kernel<<<128, 256>>>((float4*)pooled, N_GRAPHS * 128 / 4);
    fc_ln_pool<<<(N_NODES + FC_ROWS - 1) / FC_ROWS, 128>>>(
        h3, Wfc, bfc, lng, lnb, batch, x_atom, pooled, N_NODES);
}

// round 5
// speedup vs baseline: 1.6242x; 1.3766x over previous
#include <cuda_runtime.h>
#include <cuda_bf16.h>
#include <cstdint>

#define N_NODES 50000
#define N_EDGES 800000
#define N_GRAPHS 1024

// Scratch (device globals: allocation-free rule)
__device__ float g_aggr[(size_t)N_NODES * 512];
__device__ float g_h1[(size_t)N_NODES * 256];
__device__ float g_h2[(size_t)N_NODES * 512];
__device__ float g_h3[(size_t)N_NODES * 512];

// Preconverted transposed weights, bf16 hi/lo, layout [M][Kpad]:
// W1r:0 (256x128)  W1o:32768  W2r:65536 (512x256)  W2o:196608
// W3r:327680 (512x512)  W3o:589824   total 851968
__device__ __nv_bfloat16 g_wt_hi[851968];
__device__ __nv_bfloat16 g_wt_lo[851968];

// ---------------------------------------------------------------------------
// Zero kernel
// ---------------------------------------------------------------------------
__global__ void zero_kernel(float4* __restrict__ p, int n4) {
    int i = blockIdx.x * blockDim.x + threadIdx.x;
    int stride = gridDim.x * blockDim.x;
    float4 z = make_float4(0.f, 0.f, 0.f, 0.f);
    for (; i < n4; i += stride) p[i] = z;
}

// ---------------------------------------------------------------------------
// Weight prep: W [K,M] fp32 -> Wt hi/lo [M,Kpad] bf16 (transposed, padded)
// ---------------------------------------------------------------------------
__global__ void prep_wt(const float* __restrict__ W,
                        __nv_bfloat16* __restrict__ hi,
                        __nv_bfloat16* __restrict__ lo,
                        int K, int M, int Kpad) {
    int idx = blockIdx.x * blockDim.x + threadIdx.x;
    if (idx >= M * Kpad) return;
    int n = idx / Kpad, k = idx % Kpad;
    float v = (k < K) ? W[(size_t)k * M + n] : 0.f;
    __nv_bfloat16 h = __float2bfloat16(v);
    hi[idx] = h;
    lo[idx] = __float2bfloat16(v - __bfloat162float(h));
}

// ---------------------------------------------------------------------------
// Edge scatter: aggr[dst] += x[src].  Warp per edge.  int32 indices.
// ---------------------------------------------------------------------------
__global__ void scatter78(const float* __restrict__ x,
                          const int* __restrict__ ei,
                          float* __restrict__ aggr) {
    int e = (blockIdx.x * blockDim.x + threadIdx.x) >> 5;
    int lane = threadIdx.x & 31;
    if (e >= N_EDGES) return;
    int s = ei[e];
    int t = ei[N_EDGES + e];
    const float2* xs = (const float2*)(x + (size_t)s * 78);
    float2* ad = (float2*)(aggr + (size_t)t * 78);
    #pragma unroll 2
    for (int c = lane; c < 39; c += 32) {
        float2 v = xs[c];
        asm volatile("red.global.add.v2.f32 [%0], {%1, %2};"
                     :: "l"(ad + c), "f"(v.x), "f"(v.y) : "memory");
    }
}

__global__ void scatter_vec4(const float* __restrict__ x,
                             const int* __restrict__ ei,
                             float* __restrict__ aggr, int d) {
    int e = (blockIdx.x * blockDim.x + threadIdx.x) >> 5;
    int lane = threadIdx.x & 31;
    if (e >= N_EDGES) return;
    int s = ei[e];
    int t = ei[N_EDGES + e];
    int d4 = d >> 2;
    const float4* xs = (const float4*)(x + (size_t)s * d);
    float4* ad = (float4*)(aggr + (size_t)t * d);
    for (int c = lane; c < d4; c += 32) {
        float4 v = xs[c];
        asm volatile("red.global.add.v4.f32 [%0], {%1, %2, %3, %4};"
                     :: "l"(ad + c), "f"(v.x), "f"(v.y), "f"(v.z), "f"(v.w)
                     : "memory");
    }
}

// ---------------------------------------------------------------------------
// bf16 mma helpers
// ---------------------------------------------------------------------------
__device__ __forceinline__ void mma_bf16(float* c, const unsigned* a,
                                         unsigned b0, unsigned b1) {
    asm volatile(
        "mma.sync.aligned.m16n8k16.row.col.f32.bf16.bf16.f32 "
        "{%0,%1,%2,%3}, {%4,%5,%6,%7}, {%8,%9}, {%0,%1,%2,%3};"
        : "+f"(c[0]), "+f"(c[1]), "+f"(c[2]), "+f"(c[3])
        : "r"(a[0]), "r"(a[1]), "r"(a[2]), "r"(a[3]), "r"(b0), "r"(b1));
}

__device__ __forceinline__ void ldm_x4(unsigned* r, uint32_t addr) {
    asm volatile(
        "ldmatrix.sync.aligned.m8n8.x4.shared.b16 {%0,%1,%2,%3}, [%4];"
        : "=r"(r[0]), "=r"(r[1]), "=r"(r[2]), "=r"(r[3]) : "r"(addr));
}

__device__ __forceinline__ void ldm_x2(unsigned* r, uint32_t addr) {
    asm volatile(
        "ldmatrix.sync.aligned.m8n8.x2.shared.b16 {%0,%1}, [%2];"
        : "=r"(r[0]), "=r"(r[1]) : "r"(addr));
}

// ---------------------------------------------------------------------------
// Dual GEMM (bf16 hi/lo 3-term split) + bias + ReLU:
//   C = relu(A1 @ B1 + A2 @ B2 + bias)
// A: [N,K] fp32 row-major (converted to bf16 hi/lo in-kernel).
// B: preconverted transposed [M,Kpad] bf16 hi/lo (K contiguous = mma col-major).
// CTA tile 128x128, K chunk 32.  8 warps of 32x64.
// Smem tiles: [128 rows][40 bf16] (80B row stride -> ldmatrix conflict-free).
// ---------------------------------------------------------------------------
#define RS 40   // row stride in bf16 elems (80 bytes)

__global__ __launch_bounds__(256, 2)
void dual_gemm_bf16(const float* __restrict__ A1, const float* __restrict__ A2,
                    const __nv_bfloat16* __restrict__ B1h,
                    const __nv_bfloat16* __restrict__ B1l,
                    const __nv_bfloat16* __restrict__ B2h,
                    const __nv_bfloat16* __restrict__ B2l,
                    const float* __restrict__ bias, float* __restrict__ C,
                    int N, int K, int Kpad, int M) {
    __shared__ __align__(16) __nv_bfloat16 sAh[128 * RS];
    __shared__ __align__(16) __nv_bfloat16 sAl[128 * RS];
    __shared__ __align__(16) __nv_bfloat16 sBh[128 * RS];
    __shared__ __align__(16) __nv_bfloat16 sBl[128 * RS];

    int tid = threadIdx.x;
    int lane = tid & 31, wid = tid >> 5;
    int wr = wid & 3, wc = wid >> 2;       // 4x2 warp grid
    int m0w = wr * 32, n0w = wc * 64;
    int gid = lane >> 2, tig = lane & 3;

    int rowBase = blockIdx.y * 128;
    int colBase = blockIdx.x * 128;

    uint32_t uAh = (uint32_t)__cvta_generic_to_shared(sAh);
    uint32_t uAl = (uint32_t)__cvta_generic_to_shared(sAl);
    uint32_t uBh = (uint32_t)__cvta_generic_to_shared(sBh);
    uint32_t uBl = (uint32_t)__cvta_generic_to_shared(sBl);

    // ldmatrix lane-address components (in bytes)
    // A x4: row = (lane&7) + ((lane>>3)&1)*8, kchunk16B = lane>>4
    int a_row = (lane & 7) + ((lane >> 3) & 1) * 8;
    int a_koff = (lane >> 4) * 16;
    // B x2: row = lane&7, kchunk16B = (lane>>3)&1  (lanes 16-31 unused but valid)
    int b_row = lane & 7;
    int b_koff = ((lane >> 3) & 1) * 16;

    float acc[2][8][4];
    #pragma unroll
    for (int mt = 0; mt < 2; mt++)
        #pragma unroll
        for (int nt = 0; nt < 8; nt++)
            #pragma unroll
            for (int i = 0; i < 4; i++) acc[mt][nt][i] = 0.f;

    const int nch = (K + 31) >> 5;

    #pragma unroll 1
    for (int pass = 0; pass < 2; ++pass) {
        const float* A = pass ? A2 : A1;
        const __nv_bfloat16* BH = pass ? B2h : B1h;
        const __nv_bfloat16* BL = pass ? B2l : B1l;
        #pragma unroll 1
        for (int ch = 0; ch < nch; ++ch) {
            int k0 = ch << 5;
            // ---- A tile: each thread loads 16 fp32 of one row-half ----
            {
                int r = tid >> 1;
                int half = tid & 1;
                int gr = rowBase + r;
                int kb = k0 + half * 16;
                const float* arow = A + (size_t)gr * K;
                unsigned ph[8], pl[8];
                #pragma unroll
                for (int j = 0; j < 8; ++j) {
                    int ka = kb + 2 * j, kb2 = kb + 2 * j + 1;
                    float v0 = (gr < N && ka < K) ? __ldg(arow + ka) : 0.f;
                    float v1 = (gr < N && kb2 < K) ? __ldg(arow + kb2) : 0.f;
                    __nv_bfloat162 h2 = __floats2bfloat162_rn(v0, v1);
                    float r0 = v0 - __bfloat162float(h2.x);
                    float r1 = v1 - __bfloat162float(h2.y);
                    __nv_bfloat162 l2 = __floats2bfloat162_rn(r0, r1);
                    ph[j] = *(unsigned*)&h2;
                    pl[j] = *(unsigned*)&l2;
                }
                uint4* dh = (uint4*)(sAh + r * RS + half * 16);
                uint4* dl = (uint4*)(sAl + r * RS + half * 16);
                dh[0] = make_uint4(ph[0], ph[1], ph[2], ph[3]);
                dh[1] = make_uint4(ph[4], ph[5], ph[6], ph[7]);
                dl[0] = make_uint4(pl[0], pl[1], pl[2], pl[3]);
                dl[1] = make_uint4(pl[4], pl[5], pl[6], pl[7]);
            }
            // ---- B tile: 128 rows x 32 bf16 hi + lo (16B chunk copies) ----
            #pragma unroll
            for (int i = 0; i < 2; ++i) {
                int lin = tid + i * 256;      // 0..511
                int n = lin >> 2, cch = lin & 3;
                size_t so = (size_t)(colBase + n) * Kpad + k0 + cch * 8;
                *(uint4*)(sBh + n * RS + cch * 8) = *(const uint4*)(BH + so);
                *(uint4*)(sBl + n * RS + cch * 8) = *(const uint4*)(BL + so);
            }
            __syncthreads();

            // ---- Compute: 2 k16 steps ----
            #pragma unroll
            for (int ks = 0; ks < 2; ++ks) {
                int kb = ks * 32;             // byte offset of k16 step
                unsigned ah[2][4], al[2][4];
                #pragma unroll
                for (int mt = 0; mt < 2; mt++) {
                    uint32_t ao = (uint32_t)((m0w + mt * 16 + a_row) * (RS * 2)
                                             + kb + a_koff);
                    ldm_x4(ah[mt], uAh + ao);
                    ldm_x4(al[mt], uAl + ao);
                }
                #pragma unroll
                for (int nt = 0; nt < 8; nt++) {
                    uint32_t bo = (uint32_t)((n0w + nt * 8 + b_row) * (RS * 2)
                                             + kb + b_koff);
                    unsigned bh[2], bl[2];
                    ldm_x2(bh, uBh + bo);
                    ldm_x2(bl, uBl + bo);
                    #pragma unroll
                    for (int mt = 0; mt < 2; mt++) {
                        mma_bf16(acc[mt][nt], ah[mt], bh[0], bh[1]);
                        mma_bf16(acc[mt][nt], al[mt], bh[0], bh[1]);
                        mma_bf16(acc[mt][nt], ah[mt], bl[0], bl[1]);
                    }
                }
            }
            __syncthreads();
        }
    }

    // ---- Epilogue: bias + ReLU ----
    #pragma unroll
    for (int mt = 0; mt < 2; mt++) {
        #pragma unroll
        for (int nt = 0; nt < 8; nt++) {
            int r = rowBase + m0w + mt * 16 + gid;
            int c = colBase + n0w + nt * 8 + tig * 2;
            float b0v = bias[c], b1v = bias[c + 1];
            if (r < N) {
                float v0 = acc[mt][nt][0] + b0v;
                float v1 = acc[mt][nt][1] + b1v;
                C[(size_t)r * M + c]     = v0 > 0.f ? v0 : 0.f;
                C[(size_t)r * M + c + 1] = v1 > 0.f ? v1 : 0.f;
            }
            int r2 = r + 8;
            if (r2 < N) {
                float v2 = acc[mt][nt][2] + b0v;
                float v3 = acc[mt][nt][3] + b1v;
                C[(size_t)r2 * M + c]     = v2 > 0.f ? v2 : 0.f;
                C[(size_t)r2 * M + c + 1] = v3 > 0.f ? v3 : 0.f;
            }
        }
    }
}

// ---------------------------------------------------------------------------
// FC (512->128) + LayerNorm(128) + ReLU + graph pooling (sorted batch).
// ---------------------------------------------------------------------------
#define FC_ROWS 16

__global__ __launch_bounds__(128)
void fc_ln_pool(const float* __restrict__ h, const float* __restrict__ W,
                const float* __restrict__ bfc, const float* __restrict__ lng,
                const float* __restrict__ lnb,
                const int* __restrict__ batch,
                float* __restrict__ xa, float* __restrict__ pooled, int N) {
    __shared__ float sh[FC_ROWS][512];
    __shared__ float ws[4], ws2[4];

    int c = threadIdx.x;
    int lane = c & 31;
    int wid = c >> 5;
    int r0 = blockIdx.x * FC_ROWS;
    int nr = min(FC_ROWS, N - r0);

    for (int r = 0; r < nr; ++r) {
        const float4* src = (const float4*)(h + (size_t)(r0 + r) * 512);
        ((float4*)sh[r])[c] = src[c];
    }
    __syncthreads();

    float acc[FC_ROWS];
    #pragma unroll
    for (int r = 0; r < FC_ROWS; r++) acc[r] = 0.f;

    #pragma unroll 4
    for (int k = 0; k < 512; ++k) {
        float w = W[(size_t)k * 128 + c];
        #pragma unroll
        for (int r = 0; r < FC_ROWS; r++) acc[r] += sh[r][k] * w;
    }

    float pacc = 0.f;
    int curg = -1;
    for (int r = 0; r < nr; ++r) {
        float v = acc[r] + bfc[c];
        float s = v, s2 = v * v;
        #pragma unroll
        for (int o = 16; o > 0; o >>= 1) {
            s  += __shfl_xor_sync(0xffffffffu, s, o);
            s2 += __shfl_xor_sync(0xffffffffu, s2, o);
        }
        __syncthreads();
        if (lane == 0) { ws[wid] = s; ws2[wid] = s2; }
        __syncthreads();
        float sum = ws[0] + ws[1] + ws[2] + ws[3];
        float sum2 = ws2[0] + ws2[1] + ws2[2] + ws2[3];
        float mu = sum * (1.f / 128.f);
        float var = sum2 * (1.f / 128.f) - mu * mu;
        float z = (v - mu) * rsqrtf(var + 1e-5f) * lng[c] + lnb[c];
        float relu = z > 0.f ? z : 0.f;
        xa[(size_t)(r0 + r) * 128 + c] = relu;

        int g = batch[r0 + r];
        if (g != curg) {
            if (curg >= 0) atomicAdd(&pooled[(size_t)curg * 128 + c], pacc);
            curg = g;
            pacc = 0.f;
        }
        pacc += relu;
    }
    if (curg >= 0) atomicAdd(&pooled[(size_t)curg * 128 + c], pacc);
}

// ---------------------------------------------------------------------------
// Launch
// ---------------------------------------------------------------------------
extern "C" void kernel_launch(void* const* d_in, const int* in_sizes, int n_in,
                              void* d_out, int out_size) {
    const float* x     = (const float*)d_in[0];
    const int*   ei    = (const int*)d_in[1];
    const int*   batch = (const int*)d_in[2];
    const float* W1r = (const float*)d_in[3];
    const float* b1  = (const float*)d_in[4];
    const float* W1o = (const float*)d_in[5];
    const float* W2r = (const float*)d_in[6];
    const float* b2  = (const float*)d_in[7];
    const float* W2o = (const float*)d_in[8];
    const float* W3r = (const float*)d_in[9];
    const float* b3  = (const float*)d_in[10];
    const float* W3o = (const float*)d_in[11];
    const float* Wfc = (const float*)d_in[12];
    const float* bfc = (const float*)d_in[13];
    const float* lng = (const float*)d_in[14];
    const float* lnb = (const float*)d_in[15];

    float* out = (float*)d_out;
    float* x_atom = out;
    float* pooled = out + (size_t)N_NODES * 128;

    float *aggr, *h1, *h2, *h3;
    __nv_bfloat16 *wth, *wtl;
    cudaGetSymbolAddress((void**)&aggr, g_aggr);
    cudaGetSymbolAddress((void**)&h1, g_h1);
    cudaGetSymbolAddress((void**)&h2, g_h2);
    cudaGetSymbolAddress((void**)&h3, g_h3);
    cudaGetSymbolAddress((void**)&wth, g_wt_hi);
    cudaGetSymbolAddress((void**)&wtl, g_wt_lo);

    const int scatterBlocks = (N_EDGES * 32 + 255) / 256;
    const int gridY = (N_NODES + 127) / 128;

    // ---- Weight prep (bf16 hi/lo, transposed, padded) ----
    prep_wt<<<(256 * 128 + 255) / 256, 256>>>(W1r, wth + 0,      wtl + 0,      78, 256, 128);
    prep_wt<<<(256 * 128 + 255) / 256, 256>>>(W1o, wth + 32768,  wtl + 32768,  78, 256, 128);
    prep_wt<<<(512 * 256 + 255) / 256, 256>>>(W2r, wth + 65536,  wtl + 65536,  256, 512, 256);
    prep_wt<<<(512 * 256 + 255) / 256, 256>>>(W2o, wth + 196608, wtl + 196608, 256, 512, 256);
    prep_wt<<<(512 * 512 + 255) / 256, 256>>>(W3r, wth + 327680, wtl + 327680, 512, 512, 512);
    prep_wt<<<(512 * 512 + 255) / 256, 256>>>(W3o, wth + 589824, wtl + 589824, 512, 512, 512);

    // ---- Layer 1: 78 -> 256 ----
    zero_kernel<<<2048, 256>>>((float4*)aggr, N_NODES * 78 / 4);
    scatter78<<<scatterBlocks, 256>>>(x, ei, aggr);
    {
        dim3 grid(2, gridY);
        dual_gemm_bf16<<<grid, 256>>>(aggr, x,
                                      wth + 0, wtl + 0,
                                      wth + 32768, wtl + 32768,
                                      b1, h1, N_NODES, 78, 128, 256);
    }

    // ---- Layer 2: 256 -> 512 ----
    zero_kernel<<<2048, 256>>>((float4*)aggr, N_NODES * 256 / 4);
    scatter_vec4<<<scatterBlocks, 256>>>(h1, ei, aggr, 256);
    {
        dim3 grid(4, gridY);
        dual_gemm_bf16<<<grid, 256>>>(aggr, h1,
                                      wth + 65536, wtl + 65536,
                                      wth + 196608, wtl + 196608,
                                      b2, h2, N_NODES, 256, 256, 512);
    }

    // ---- Layer 3: 512 -> 512 ----
    zero_kernel<<<2048, 256>>>((float4*)aggr, N_NODES * 512 / 4);
    scatter_vec4<<<scatterBlocks, 256>>>(h2, ei, aggr, 512);
    {
        dim3 grid(4, gridY);
        dual_gemm_bf16<<<grid, 256>>>(aggr, h2,
                                      wth + 327680, wtl + 327680,
                                      wth + 589824, wtl + 589824,
                                      b3, h3, N_NODES, 512, 512, 512);
    }

    // ---- FC + LayerNorm + ReLU + pooling ----
    zero_kernel<<<128, 256>>>((float4*)pooled, N_GRAPHS * 128 / 4);
    fc_ln_pool<<<(N_NODES + FC_ROWS - 1) / FC_ROWS, 128>>>(
        h3, Wfc, bfc, lng, lnb, batch, x_atom, pooled, N_NODES);
}

// round 6
// speedup vs baseline: 2.2991x; 1.4155x over previous
#include <cuda_runtime.h>
#include <cuda_bf16.h>
#include <cstdint>

#define N_NODES 50000
#define N_EDGES 800000
#define N_GRAPHS 1024

// ---------------- device-global scratch (allocation-free rule) -------------
__device__ float g_h1[(size_t)N_NODES * 256];
__device__ float g_h2[(size_t)N_NODES * 512];
__device__ float g_h3[(size_t)N_NODES * 512];
__device__ __nv_bfloat16 g_agg_hi[(size_t)N_NODES * 512];
__device__ __nv_bfloat16 g_agg_lo[(size_t)N_NODES * 512];
__device__ __nv_bfloat16 g_bufA_hi[(size_t)N_NODES * 512];
__device__ __nv_bfloat16 g_bufA_lo[(size_t)N_NODES * 512];
__device__ __nv_bfloat16 g_bufB_hi[(size_t)N_NODES * 512];
__device__ __nv_bfloat16 g_bufB_lo[(size_t)N_NODES * 512];
// transposed weights bf16 hi/lo [M][Kpad]
__device__ __nv_bfloat16 g_wt_hi[851968];
__device__ __nv_bfloat16 g_wt_lo[851968];
// CSR
__device__ int g_cnt[N_NODES];
__device__ int g_off[N_NODES + 1];
__device__ int g_cur[N_NODES];
__device__ int g_srcs[N_EDGES];
__device__ int g_bsum[64];

// ---------------------------------------------------------------------------
__global__ void zero_kernel(float4* __restrict__ p, int n4) {
    int i = blockIdx.x * blockDim.x + threadIdx.x;
    int stride = gridDim.x * blockDim.x;
    float4 z = make_float4(0.f, 0.f, 0.f, 0.f);
    for (; i < n4; i += stride) p[i] = z;
}

__global__ void zero_int(int* __restrict__ p, int n) {
    int i = blockIdx.x * blockDim.x + threadIdx.x;
    if (i < n) p[i] = 0;
}

// ---------------------------------------------------------------------------
// Weight prep: W [K,M] fp32 -> Wt hi/lo [M,Kpad] bf16 (transposed, padded)
// ---------------------------------------------------------------------------
__global__ void prep_wt(const float* __restrict__ W,
                        __nv_bfloat16* __restrict__ hi,
                        __nv_bfloat16* __restrict__ lo,
                        int K, int M, int Kpad) {
    int idx = blockIdx.x * blockDim.x + threadIdx.x;
    if (idx >= M * Kpad) return;
    int n = idx / Kpad, k = idx % Kpad;
    float v = (k < K) ? W[(size_t)k * M + n] : 0.f;
    __nv_bfloat16 h = __float2bfloat16(v);
    hi[idx] = h;
    lo[idx] = __float2bfloat16(v - __bfloat162float(h));
}

// x [N,78] fp32 -> hi/lo [N,128] bf16 padded
__global__ void prep_x(const float* __restrict__ x,
                       __nv_bfloat16* __restrict__ hi,
                       __nv_bfloat16* __restrict__ lo) {
    int idx = blockIdx.x * blockDim.x + threadIdx.x;
    if (idx >= N_NODES * 128) return;
    int n = idx >> 7, k = idx & 127;
    float v = (k < 78) ? x[(size_t)n * 78 + k] : 0.f;
    __nv_bfloat16 h = __float2bfloat16(v);
    hi[idx] = h;
    lo[idx] = __float2bfloat16(v - __bfloat162float(h));
}

// ---------------------------------------------------------------------------
// CSR build: histogram -> exclusive scan -> fill
// ---------------------------------------------------------------------------
__global__ void hist_kernel(const int* __restrict__ ei) {
    int e = blockIdx.x * blockDim.x + threadIdx.x;
    if (e < N_EDGES) atomicAdd(&g_cnt[ei[N_EDGES + e]], 1);
}

__global__ void scan1(void) {
    __shared__ int sm[1024];
    int tid = threadIdx.x;
    int i = blockIdx.x * 1024 + tid;
    int v = (i < N_NODES) ? g_cnt[i] : 0;
    sm[tid] = v;
    __syncthreads();
    for (int o = 1; o < 1024; o <<= 1) {
        int t = (tid >= o) ? sm[tid - o] : 0;
        __syncthreads();
        sm[tid] += t;
        __syncthreads();
    }
    if (i < N_NODES) g_off[i] = sm[tid] - v;   // exclusive within block
    if (tid == 1023) g_bsum[blockIdx.x] = sm[1023];
}

__global__ void scan2(int nblk) {
    if (threadIdx.x == 0) {
        int run = 0;
        for (int b = 0; b < nblk; ++b) {
            int t = g_bsum[b];
            g_bsum[b] = run;
            run += t;
        }
    }
}

__global__ void scan3(void) {
    int i = blockIdx.x * blockDim.x + threadIdx.x;
    if (i < N_NODES) {
        int o = g_off[i] + g_bsum[i >> 10];
        g_off[i] = o;
        g_cur[i] = o;
    }
    if (i == 0) g_off[N_NODES] = N_EDGES;
}

__global__ void fill_kernel(const int* __restrict__ ei) {
    int e = blockIdx.x * blockDim.x + threadIdx.x;
    if (e >= N_EDGES) return;
    int s = ei[e], t = ei[N_EDGES + e];
    int pos = atomicAdd(&g_cur[t], 1);
    g_srcs[pos] = s;
}

// ---------------------------------------------------------------------------
// CSR gather: aggr[n] = sum_{j in off[n]..off[n+1]} x[srcs[j]]
// Output directly as bf16 hi/lo.  Warp per node.
// ---------------------------------------------------------------------------
__global__ void gather78(const float* __restrict__ x,
                         __nv_bfloat16* __restrict__ ahi,
                         __nv_bfloat16* __restrict__ alo) {
    int n = (blockIdx.x * blockDim.x + threadIdx.x) >> 5;
    int lane = threadIdx.x & 31;
    if (n >= N_NODES) return;
    int jb = g_off[n], je = g_off[n + 1];
    float a0 = 0.f, a1 = 0.f, a2 = 0.f;
    for (int j = jb; j < je; ++j) {
        const float* xr = x + (size_t)g_srcs[j] * 78;
        a0 += __ldg(xr + lane);
        a1 += __ldg(xr + lane + 32);
        if (lane < 14) a2 += __ldg(xr + lane + 64);
    }
    size_t base = (size_t)n * 128;
    float vals[4] = {a0, a1, (lane < 14) ? a2 : 0.f, 0.f};
    #pragma unroll
    for (int i = 0; i < 4; ++i) {
        __nv_bfloat16 h = __float2bfloat16(vals[i]);
        ahi[base + lane + i * 32] = h;
        alo[base + lane + i * 32] = __float2bfloat16(vals[i] - __bfloat162float(h));
    }
}

__global__ void gather_vec4(const float* __restrict__ x, int d,
                            __nv_bfloat16* __restrict__ ahi,
                            __nv_bfloat16* __restrict__ alo) {
    int n = (blockIdx.x * blockDim.x + threadIdx.x) >> 5;
    int lane = threadIdx.x & 31;
    if (n >= N_NODES) return;
    int jb = g_off[n], je = g_off[n + 1];
    int ni = d >> 7;                       // float4 groups per lane (2 or 4)
    float4 acc[4];
    #pragma unroll
    for (int i = 0; i < 4; ++i) acc[i] = make_float4(0.f, 0.f, 0.f, 0.f);
    for (int j = jb; j < je; ++j) {
        const float4* xr = (const float4*)(x + (size_t)g_srcs[j] * d);
        #pragma unroll 4
        for (int i = 0; i < ni; ++i) {
            float4 v = __ldg(xr + lane + i * 32);
            acc[i].x += v.x; acc[i].y += v.y; acc[i].z += v.z; acc[i].w += v.w;
        }
    }
    for (int i = 0; i < ni; ++i) {
        int c = (lane + i * 32) * 4;
        float4 a = acc[i];
        __nv_bfloat162 h01 = __floats2bfloat162_rn(a.x, a.y);
        __nv_bfloat162 h23 = __floats2bfloat162_rn(a.z, a.w);
        __nv_bfloat162 l01 = __floats2bfloat162_rn(a.x - __bfloat162float(h01.x),
                                                   a.y - __bfloat162float(h01.y));
        __nv_bfloat162 l23 = __floats2bfloat162_rn(a.z - __bfloat162float(h23.x),
                                                   a.w - __bfloat162float(h23.y));
        *(uint2*)(ahi + (size_t)n * d + c) =
            make_uint2(*(unsigned*)&h01, *(unsigned*)&h23);
        *(uint2*)(alo + (size_t)n * d + c) =
            make_uint2(*(unsigned*)&l01, *(unsigned*)&l23);
    }
}

// ---------------------------------------------------------------------------
// bf16 mma helpers
// ---------------------------------------------------------------------------
__device__ __forceinline__ void mma_bf16(float* c, const unsigned* a,
                                         unsigned b0, unsigned b1) {
    asm volatile(
        "mma.sync.aligned.m16n8k16.row.col.f32.bf16.bf16.f32 "
        "{%0,%1,%2,%3}, {%4,%5,%6,%7}, {%8,%9}, {%0,%1,%2,%3};"
        : "+f"(c[0]), "+f"(c[1]), "+f"(c[2]), "+f"(c[3])
        : "r"(a[0]), "r"(a[1]), "r"(a[2]), "r"(a[3]), "r"(b0), "r"(b1));
}

__device__ __forceinline__ void ldm_x4(unsigned* r, uint32_t addr) {
    asm volatile(
        "ldmatrix.sync.aligned.m8n8.x4.shared.b16 {%0,%1,%2,%3}, [%4];"
        : "=r"(r[0]), "=r"(r[1]), "=r"(r[2]), "=r"(r[3]) : "r"(addr));
}

__device__ __forceinline__ void ldm_x2(unsigned* r, uint32_t addr) {
    asm volatile(
        "ldmatrix.sync.aligned.m8n8.x2.shared.b16 {%0,%1}, [%2];"
        : "=r"(r[0]), "=r"(r[1]) : "r"(addr));
}

// ---------------------------------------------------------------------------
// Dual GEMM (bf16 hi/lo 3-term split) + bias + ReLU:
//   C = relu(A1 @ B1 + A2 @ B2 + bias)
// All operands preconverted bf16 hi/lo, [rows][Kpad], K contiguous.
// Optional bf16 hi/lo output (Chi/Clo) for next layer's root operand.
// CTA tile 128x128, K chunk 32.  8 warps of 32x64.
// Smem tiles: [128 rows][40 bf16] (80B row stride -> ldmatrix conflict-free).
// ---------------------------------------------------------------------------
#define RS 40

__global__ __launch_bounds__(256, 2)
void dual_gemm_bf16(const __nv_bfloat16* __restrict__ A1h,
                    const __nv_bfloat16* __restrict__ A1l,
                    const __nv_bfloat16* __restrict__ A2h,
                    const __nv_bfloat16* __restrict__ A2l,
                    const __nv_bfloat16* __restrict__ B1h,
                    const __nv_bfloat16* __restrict__ B1l,
                    const __nv_bfloat16* __restrict__ B2h,
                    const __nv_bfloat16* __restrict__ B2l,
                    const float* __restrict__ bias, float* __restrict__ C,
                    __nv_bfloat16* __restrict__ Chi,
                    __nv_bfloat16* __restrict__ Clo,
                    int N, int Kpad, int M) {
    __shared__ __align__(16) __nv_bfloat16 sAh[128 * RS];
    __shared__ __align__(16) __nv_bfloat16 sAl[128 * RS];
    __shared__ __align__(16) __nv_bfloat16 sBh[128 * RS];
    __shared__ __align__(16) __nv_bfloat16 sBl[128 * RS];

    int tid = threadIdx.x;
    int lane = tid & 31, wid = tid >> 5;
    int wr = wid & 3, wc = wid >> 2;
    int m0w = wr * 32, n0w = wc * 64;
    int gid = lane >> 2, tig = lane & 3;

    int rowBase = blockIdx.y * 128;
    int colBase = blockIdx.x * 128;

    uint32_t uAh = (uint32_t)__cvta_generic_to_shared(sAh);
    uint32_t uAl = (uint32_t)__cvta_generic_to_shared(sAl);
    uint32_t uBh = (uint32_t)__cvta_generic_to_shared(sBh);
    uint32_t uBl = (uint32_t)__cvta_generic_to_shared(sBl);

    int a_row = (lane & 7) + ((lane >> 3) & 1) * 8;
    int a_koff = (lane >> 4) * 16;
    int b_row = lane & 7;
    int b_koff = ((lane >> 3) & 1) * 16;

    float acc[2][8][4];
    #pragma unroll
    for (int mt = 0; mt < 2; mt++)
        #pragma unroll
        for (int nt = 0; nt < 8; nt++)
            #pragma unroll
            for (int i = 0; i < 4; i++) acc[mt][nt][i] = 0.f;

    const int nch = Kpad >> 5;
    // chunk-copy indices: 512 (row, 16B-chunk) pairs over 2 iterations
    int cr = tid >> 1;            // unused placeholder removed below

    #pragma unroll 1
    for (int pass = 0; pass < 2; ++pass) {
        const __nv_bfloat16* AH = pass ? A2h : A1h;
        const __nv_bfloat16* AL = pass ? A2l : A1l;
        const __nv_bfloat16* BH = pass ? B2h : B1h;
        const __nv_bfloat16* BL = pass ? B2l : B1l;
        #pragma unroll 1
        for (int ch = 0; ch < nch; ++ch) {
            int k0 = ch << 5;
            // ---- A tile: 128 rows x 32 bf16 hi+lo (16B chunk copies) ----
            #pragma unroll
            for (int i = 0; i < 2; ++i) {
                int lin = tid + i * 256;
                int r = lin >> 2, cch = lin & 3;
                int gr = rowBase + r;
                uint4 vh, vl;
                if (gr < N) {
                    size_t so = (size_t)gr * Kpad + k0 + cch * 8;
                    vh = *(const uint4*)(AH + so);
                    vl = *(const uint4*)(AL + so);
                } else {
                    vh = make_uint4(0, 0, 0, 0);
                    vl = make_uint4(0, 0, 0, 0);
                }
                *(uint4*)(sAh + r * RS + cch * 8) = vh;
                *(uint4*)(sAl + r * RS + cch * 8) = vl;
            }
            // ---- B tile ----
            #pragma unroll
            for (int i = 0; i < 2; ++i) {
                int lin = tid + i * 256;
                int n = lin >> 2, cch = lin & 3;
                size_t so = (size_t)(colBase + n) * Kpad + k0 + cch * 8;
                *(uint4*)(sBh + n * RS + cch * 8) = *(const uint4*)(BH + so);
                *(uint4*)(sBl + n * RS + cch * 8) = *(const uint4*)(BL + so);
            }
            __syncthreads();

            #pragma unroll
            for (int ks = 0; ks < 2; ++ks) {
                int kb = ks * 32;
                unsigned ah[2][4], al[2][4];
                #pragma unroll
                for (int mt = 0; mt < 2; mt++) {
                    uint32_t ao = (uint32_t)((m0w + mt * 16 + a_row) * (RS * 2)
                                             + kb + a_koff);
                    ldm_x4(ah[mt], uAh + ao);
                    ldm_x4(al[mt], uAl + ao);
                }
                #pragma unroll
                for (int nt = 0; nt < 8; nt++) {
                    uint32_t bo = (uint32_t)((n0w + nt * 8 + b_row) * (RS * 2)
                                             + kb + b_koff);
                    unsigned bh[2], bl[2];
                    ldm_x2(bh, uBh + bo);
                    ldm_x2(bl, uBl + bo);
                    #pragma unroll
                    for (int mt = 0; mt < 2; mt++) {
                        mma_bf16(acc[mt][nt], ah[mt], bh[0], bh[1]);
                        mma_bf16(acc[mt][nt], al[mt], bh[0], bh[1]);
                        mma_bf16(acc[mt][nt], ah[mt], bl[0], bl[1]);
                    }
                }
            }
            __syncthreads();
        }
    }

    // ---- Epilogue: bias + ReLU (+ optional bf16 hi/lo copy) ----
    #pragma unroll
    for (int mt = 0; mt < 2; mt++) {
        #pragma unroll
        for (int nt = 0; nt < 8; nt++) {
            int r = rowBase + m0w + mt * 16 + gid;
            int c = colBase + n0w + nt * 8 + tig * 2;
            float b0v = bias[c], b1v = bias[c + 1];
            #pragma unroll
            for (int half = 0; half < 2; ++half) {
                int rr = r + half * 8;
                if (rr >= N) continue;
                float v0 = acc[mt][nt][2 * half + 0] + b0v;
                float v1 = acc[mt][nt][2 * half + 1] + b1v;
                v0 = v0 > 0.f ? v0 : 0.f;
                v1 = v1 > 0.f ? v1 : 0.f;
                size_t o = (size_t)rr * M + c;
                C[o] = v0;
                C[o + 1] = v1;
                if (Chi) {
                    __nv_bfloat162 hh = __floats2bfloat162_rn(v0, v1);
                    __nv_bfloat162 ll = __floats2bfloat162_rn(
                        v0 - __bfloat162float(hh.x), v1 - __bfloat162float(hh.y));
                    *(unsigned*)(Chi + o) = *(unsigned*)&hh;
                    *(unsigned*)(Clo + o) = *(unsigned*)&ll;
                }
            }
        }
    }
}

// ---------------------------------------------------------------------------
// FC (512->128) + LayerNorm(128) + ReLU + graph pooling (sorted batch).
// ---------------------------------------------------------------------------
#define FC_ROWS 16

__global__ __launch_bounds__(128)
void fc_ln_pool(const float* __restrict__ h, const float* __restrict__ W,
                const float* __restrict__ bfc, const float* __restrict__ lng,
                const float* __restrict__ lnb,
                const int* __restrict__ batch,
                float* __restrict__ xa, float* __restrict__ pooled, int N) {
    __shared__ float sh[FC_ROWS][512];
    __shared__ float ws[4], ws2[4];

    int c = threadIdx.x;
    int lane = c & 31;
    int wid = c >> 5;
    int r0 = blockIdx.x * FC_ROWS;
    int nr = min(FC_ROWS, N - r0);

    for (int r = 0; r < nr; ++r) {
        const float4* src = (const float4*)(h + (size_t)(r0 + r) * 512);
        ((float4*)sh[r])[c] = src[c];
    }
    __syncthreads();

    float acc[FC_ROWS];
    #pragma unroll
    for (int r = 0; r < FC_ROWS; r++) acc[r] = 0.f;

    #pragma unroll 4
    for (int k = 0; k < 512; ++k) {
        float w = W[(size_t)k * 128 + c];
        #pragma unroll
        for (int r = 0; r < FC_ROWS; r++) acc[r] += sh[r][k] * w;
    }

    float pacc = 0.f;
    int curg = -1;
    for (int r = 0; r < nr; ++r) {
        float v = acc[r] + bfc[c];
        float s = v, s2 = v * v;
        #pragma unroll
        for (int o = 16; o > 0; o >>= 1) {
            s  += __shfl_xor_sync(0xffffffffu, s, o);
            s2 += __shfl_xor_sync(0xffffffffu, s2, o);
        }
        __syncthreads();
        if (lane == 0) { ws[wid] = s; ws2[wid] = s2; }
        __syncthreads();
        float sum = ws[0] + ws[1] + ws[2] + ws[3];
        float sum2 = ws2[0] + ws2[1] + ws2[2] + ws2[3];
        float mu = sum * (1.f / 128.f);
        float var = sum2 * (1.f / 128.f) - mu * mu;
        float z = (v - mu) * rsqrtf(var + 1e-5f) * lng[c] + lnb[c];
        float relu = z > 0.f ? z : 0.f;
        xa[(size_t)(r0 + r) * 128 + c] = relu;

        int g = batch[r0 + r];
        if (g != curg) {
            if (curg >= 0) atomicAdd(&pooled[(size_t)curg * 128 + c], pacc);
            curg = g;
            pacc = 0.f;
        }
        pacc += relu;
    }
    if (curg >= 0) atomicAdd(&pooled[(size_t)curg * 128 + c], pacc);
}

// ---------------------------------------------------------------------------
// Launch
// ---------------------------------------------------------------------------
extern "C" void kernel_launch(void* const* d_in, const int* in_sizes, int n_in,
                              void* d_out, int out_size) {
    const float* x     = (const float*)d_in[0];
    const int*   ei    = (const int*)d_in[1];
    const int*   batch = (const int*)d_in[2];
    const float* W1r = (const float*)d_in[3];
    const float* b1  = (const float*)d_in[4];
    const float* W2r = (const float*)d_in[6];
    const float* b2  = (const float*)d_in[7];
    const float* W3r = (const float*)d_in[9];
    const float* b3  = (const float*)d_in[10];
    const float* W1o = (const float*)d_in[5];
    const float* W2o = (const float*)d_in[8];
    const float* W3o = (const float*)d_in[11];
    const float* Wfc = (const float*)d_in[12];
    const float* bfc = (const float*)d_in[13];
    const float* lng = (const float*)d_in[14];
    const float* lnb = (const float*)d_in[15];

    float* out = (float*)d_out;
    float* x_atom = out;
    float* pooled = out + (size_t)N_NODES * 128;

    float *h1, *h2, *h3;
    __nv_bfloat16 *aggh, *aggl, *bAh, *bAl, *bBh, *bBl, *wth, *wtl;
    cudaGetSymbolAddress((void**)&h1, g_h1);
    cudaGetSymbolAddress((void**)&h2, g_h2);
    cudaGetSymbolAddress((void**)&h3, g_h3);
    cudaGetSymbolAddress((void**)&aggh, g_agg_hi);
    cudaGetSymbolAddress((void**)&aggl, g_agg_lo);
    cudaGetSymbolAddress((void**)&bAh, g_bufA_hi);
    cudaGetSymbolAddress((void**)&bAl, g_bufA_lo);
    cudaGetSymbolAddress((void**)&bBh, g_bufB_hi);
    cudaGetSymbolAddress((void**)&bBl, g_bufB_lo);
    cudaGetSymbolAddress((void**)&wth, g_wt_hi);
    cudaGetSymbolAddress((void**)&wtl, g_wt_lo);

    const int gridY = (N_NODES + 127) / 128;
    const int gatherBlocks = (N_NODES * 32 + 255) / 256;

    // ---- Weight prep ----
    prep_wt<<<(256 * 128 + 255) / 256, 256>>>(W1r, wth + 0,      wtl + 0,      78, 256, 128);
    prep_wt<<<(256 * 128 + 255) / 256, 256>>>(W1o, wth + 32768,  wtl + 32768,  78, 256, 128);
    prep_wt<<<(512 * 256 + 255) / 256, 256>>>(W2r, wth + 65536,  wtl + 65536,  256, 512, 256);
    prep_wt<<<(512 * 256 + 255) / 256, 256>>>(W2o, wth + 196608, wtl + 196608, 256, 512, 256);
    prep_wt<<<(512 * 512 + 255) / 256, 256>>>(W3r, wth + 327680, wtl + 327680, 512, 512, 512);
    prep_wt<<<(512 * 512 + 255) / 256, 256>>>(W3o, wth + 589824, wtl + 589824, 512, 512, 512);
    prep_x<<<(N_NODES * 128 + 255) / 256, 256>>>(x, bAh, bAl);

    // ---- CSR build (edges shared by all 3 layers) ----
    {
        int* pcnt; cudaGetSymbolAddress((void**)&pcnt, g_cnt);
        zero_int<<<(N_NODES + 255) / 256, 256>>>(pcnt, N_NODES);
    }
    hist_kernel<<<(N_EDGES + 255) / 256, 256>>>(ei);
    scan1<<<(N_NODES + 1023) / 1024, 1024>>>();
    scan2<<<1, 32>>>((N_NODES + 1023) / 1024);
    scan3<<<(N_NODES + 255) / 256, 256>>>();
    fill_kernel<<<(N_EDGES + 255) / 256, 256>>>(ei);

    // ---- Layer 1: 78 -> 256 ----
    gather78<<<gatherBlocks, 256>>>(x, aggh, aggl);
    {
        dim3 grid(2, gridY);
        dual_gemm_bf16<<<grid, 256>>>(aggh, aggl, bAh, bAl,
                                      wth + 0, wtl + 0, wth + 32768, wtl + 32768,
                                      b1, h1, bBh, bBl, N_NODES, 128, 256);
    }

    // ---- Layer 2: 256 -> 512 ----
    gather_vec4<<<gatherBlocks, 256>>>(h1, 256, aggh, aggl);
    {
        dim3 grid(4, gridY);
        dual_gemm_bf16<<<grid, 256>>>(aggh, aggl, bBh, bBl,
                                      wth + 65536, wtl + 65536,
                                      wth + 196608, wtl + 196608,
                                      b2, h2, bAh, bAl, N_NODES, 256, 512);
    }

    // ---- Layer 3: 512 -> 512 ----
    gather_vec4<<<gatherBlocks, 256>>>(h2, 512, aggh, aggl);
    {
        dim3 grid(4, gridY);
        dual_gemm_bf16<<<grid, 256>>>(aggh, aggl, bAh, bAl,
                                      wth + 327680, wtl + 327680,
                                      wth + 589824, wtl + 589824,
                                      b3, h3, (__nv_bfloat16*)nullptr,
                                      (__nv_bfloat16*)nullptr, N_NODES, 512, 512);
    }

    // ---- FC + LayerNorm + ReLU + pooling ----
    zero_kernel<<<128, 256>>>((float4*)pooled, N_GRAPHS * 128 / 4);
    fc_ln_pool<<<(N_NODES + FC_ROWS - 1) / FC_ROWS, 128>>>(
        h3, Wfc, bfc, lng, lnb, batch, x_atom, pooled, N_NODES);
}

// round 7
// speedup vs baseline: 2.9156x; 1.2682x over previous
#include <cuda_runtime.h>
#include <cuda_bf16.h>
#include <cstdint>

#define N_NODES 50000
#define N_EDGES 800000
#define N_GRAPHS 1024

// ---------------- device-global scratch (allocation-free rule) -------------
__device__ float g_h1[(size_t)N_NODES * 256];   // also reused for FC z output
__device__ float g_h2[(size_t)N_NODES * 512];
__device__ __nv_bfloat16 g_agg_hi[(size_t)N_NODES * 512];
__device__ __nv_bfloat16 g_agg_lo[(size_t)N_NODES * 512];
__device__ __nv_bfloat16 g_bufA_hi[(size_t)N_NODES * 512];
__device__ __nv_bfloat16 g_bufA_lo[(size_t)N_NODES * 512];
__device__ __nv_bfloat16 g_bufB_hi[(size_t)N_NODES * 512];
__device__ __nv_bfloat16 g_bufB_lo[(size_t)N_NODES * 512];
// transposed weights bf16 hi/lo [M][Kpad]
// W1r:0(256x96) W1o:24576 W2r:49152(512x256) W2o:180224
// W3r:311296(512x512) W3o:573440 Wfc:835584(128x512)  total 901120
__device__ __nv_bfloat16 g_wt_hi[901120];
__device__ __nv_bfloat16 g_wt_lo[901120];
// CSR
__device__ int g_cnt[N_NODES];
__device__ int g_off[N_NODES + 1];
__device__ int g_cur[N_NODES];
__device__ int g_srcs[N_EDGES];
__device__ int g_bsum[64];

// ---------------------------------------------------------------------------
__global__ void zero_kernel(float4* __restrict__ p, int n4) {
    int i = blockIdx.x * blockDim.x + threadIdx.x;
    int stride = gridDim.x * blockDim.x;
    float4 z = make_float4(0.f, 0.f, 0.f, 0.f);
    for (; i < n4; i += stride) p[i] = z;
}

__global__ void zero_int(int* __restrict__ p, int n) {
    int i = blockIdx.x * blockDim.x + threadIdx.x;
    if (i < n) p[i] = 0;
}

// ---------------------------------------------------------------------------
// Weight prep: W [K,M] fp32 -> Wt hi/lo [M,Kpad] bf16 (transposed, padded)
// ---------------------------------------------------------------------------
__global__ void prep_wt(const float* __restrict__ W,
                        __nv_bfloat16* __restrict__ hi,
                        __nv_bfloat16* __restrict__ lo,
                        int K, int M, int Kpad) {
    int idx = blockIdx.x * blockDim.x + threadIdx.x;
    if (idx >= M * Kpad) return;
    int n = idx / Kpad, k = idx % Kpad;
    float v = (k < K) ? W[(size_t)k * M + n] : 0.f;
    __nv_bfloat16 h = __float2bfloat16(v);
    hi[idx] = h;
    lo[idx] = __float2bfloat16(v - __bfloat162float(h));
}

// x [N,78] fp32 -> hi/lo [N,96] bf16 padded
__global__ void prep_x(const float* __restrict__ x,
                       __nv_bfloat16* __restrict__ hi,
                       __nv_bfloat16* __restrict__ lo) {
    int idx = blockIdx.x * blockDim.x + threadIdx.x;
    if (idx >= N_NODES * 96) return;
    int n = idx / 96, k = idx % 96;
    float v = (k < 78) ? x[(size_t)n * 78 + k] : 0.f;
    __nv_bfloat16 h = __float2bfloat16(v);
    hi[idx] = h;
    lo[idx] = __float2bfloat16(v - __bfloat162float(h));
}

// ---------------------------------------------------------------------------
// CSR build
// ---------------------------------------------------------------------------
__global__ void hist_kernel(const int* __restrict__ ei) {
    int e = blockIdx.x * blockDim.x + threadIdx.x;
    if (e < N_EDGES) atomicAdd(&g_cnt[ei[N_EDGES + e]], 1);
}

__global__ void scan1(void) {
    __shared__ int sm[1024];
    int tid = threadIdx.x;
    int i = blockIdx.x * 1024 + tid;
    int v = (i < N_NODES) ? g_cnt[i] : 0;
    sm[tid] = v;
    __syncthreads();
    for (int o = 1; o < 1024; o <<= 1) {
        int t = (tid >= o) ? sm[tid - o] : 0;
        __syncthreads();
        sm[tid] += t;
        __syncthreads();
    }
    if (i < N_NODES) g_off[i] = sm[tid] - v;
    if (tid == 1023) g_bsum[blockIdx.x] = sm[1023];
}

__global__ void scan2(int nblk) {
    if (threadIdx.x == 0) {
        int run = 0;
        for (int b = 0; b < nblk; ++b) {
            int t = g_bsum[b];
            g_bsum[b] = run;
            run += t;
        }
    }
}

__global__ void scan3(void) {
    int i = blockIdx.x * blockDim.x + threadIdx.x;
    if (i < N_NODES) {
        int o = g_off[i] + g_bsum[i >> 10];
        g_off[i] = o;
        g_cur[i] = o;
    }
    if (i == 0) g_off[N_NODES] = N_EDGES;
}

__global__ void fill_kernel(const int* __restrict__ ei) {
    int e = blockIdx.x * blockDim.x + threadIdx.x;
    if (e >= N_EDGES) return;
    int s = ei[e], t = ei[N_EDGES + e];
    int pos = atomicAdd(&g_cur[t], 1);
    g_srcs[pos] = s;
}

// ---------------------------------------------------------------------------
// CSR gather -> bf16 hi/lo.  Warp per node.
// ---------------------------------------------------------------------------
__global__ void gather78(const float* __restrict__ x,
                         __nv_bfloat16* __restrict__ ahi,
                         __nv_bfloat16* __restrict__ alo) {
    int n = (blockIdx.x * blockDim.x + threadIdx.x) >> 5;
    int lane = threadIdx.x & 31;
    if (n >= N_NODES) return;
    int jb = g_off[n], je = g_off[n + 1];
    float a0 = 0.f, a1 = 0.f, a2 = 0.f;
    for (int j = jb; j < je; ++j) {
        const float* xr = x + (size_t)g_srcs[j] * 78;
        a0 += __ldg(xr + lane);
        a1 += __ldg(xr + lane + 32);
        if (lane < 14) a2 += __ldg(xr + lane + 64);
    }
    size_t base = (size_t)n * 96;
    float vals[3] = {a0, a1, (lane < 14) ? a2 : 0.f};
    #pragma unroll
    for (int i = 0; i < 3; ++i) {
        __nv_bfloat16 h = __float2bfloat16(vals[i]);
        ahi[base + lane + i * 32] = h;
        alo[base + lane + i * 32] = __float2bfloat16(vals[i] - __bfloat162float(h));
    }
}

__global__ void gather_vec4(const float* __restrict__ x, int d,
                            __nv_bfloat16* __restrict__ ahi,
                            __nv_bfloat16* __restrict__ alo) {
    int n = (blockIdx.x * blockDim.x + threadIdx.x) >> 5;
    int lane = threadIdx.x & 31;
    if (n >= N_NODES) return;
    int jb = g_off[n], je = g_off[n + 1];
    int ni = d >> 7;
    float4 acc[4];
    #pragma unroll
    for (int i = 0; i < 4; ++i) acc[i] = make_float4(0.f, 0.f, 0.f, 0.f);
    for (int j = jb; j < je; ++j) {
        const float4* xr = (const float4*)(x + (size_t)g_srcs[j] * d);
        #pragma unroll 4
        for (int i = 0; i < ni; ++i) {
            float4 v = __ldg(xr + lane + i * 32);
            acc[i].x += v.x; acc[i].y += v.y; acc[i].z += v.z; acc[i].w += v.w;
        }
    }
    for (int i = 0; i < ni; ++i) {
        int c = (lane + i * 32) * 4;
        float4 a = acc[i];
        __nv_bfloat162 h01 = __floats2bfloat162_rn(a.x, a.y);
        __nv_bfloat162 h23 = __floats2bfloat162_rn(a.z, a.w);
        __nv_bfloat162 l01 = __floats2bfloat162_rn(a.x - __bfloat162float(h01.x),
                                                   a.y - __bfloat162float(h01.y));
        __nv_bfloat162 l23 = __floats2bfloat162_rn(a.z - __bfloat162float(h23.x),
                                                   a.w - __bfloat162float(h23.y));
        *(uint2*)(ahi + (size_t)n * d + c) =
            make_uint2(*(unsigned*)&h01, *(unsigned*)&h23);
        *(uint2*)(alo + (size_t)n * d + c) =
            make_uint2(*(unsigned*)&l01, *(unsigned*)&l23);
    }
}

// ---------------------------------------------------------------------------
// mma / ldmatrix / cp.async helpers
// ---------------------------------------------------------------------------
__device__ __forceinline__ void mma_bf16(float* c, const unsigned* a,
                                         unsigned b0, unsigned b1) {
    asm volatile(
        "mma.sync.aligned.m16n8k16.row.col.f32.bf16.bf16.f32 "
        "{%0,%1,%2,%3}, {%4,%5,%6,%7}, {%8,%9}, {%0,%1,%2,%3};"
        : "+f"(c[0]), "+f"(c[1]), "+f"(c[2]), "+f"(c[3])
        : "r"(a[0]), "r"(a[1]), "r"(a[2]), "r"(a[3]), "r"(b0), "r"(b1));
}

__device__ __forceinline__ void ldm_x4(unsigned* r, uint32_t addr) {
    asm volatile(
        "ldmatrix.sync.aligned.m8n8.x4.shared.b16 {%0,%1,%2,%3}, [%4];"
        : "=r"(r[0]), "=r"(r[1]), "=r"(r[2]), "=r"(r[3]) : "r"(addr));
}

__device__ __forceinline__ void ldm_x2(unsigned* r, uint32_t addr) {
    asm volatile(
        "ldmatrix.sync.aligned.m8n8.x2.shared.b16 {%0,%1}, [%2];"
        : "=r"(r[0]), "=r"(r[1]) : "r"(addr));
}

__device__ __forceinline__ void cpa16(uint32_t d, const void* s, int sz) {
    asm volatile("cp.async.cg.shared.global [%0], [%1], 16, %2;"
                 :: "r"(d), "l"(s), "r"(sz) : "memory");
}

// ---------------------------------------------------------------------------
// Dual/single GEMM (bf16 hi/lo 3-term split), cp.async double-buffered.
//   C = act(A1 @ B1 [+ A2 @ B2] + bias),  act = ReLU if do_relu
// Operands bf16 hi/lo [rows][Kpad], K contiguous.  Tiles 128x128, chunk K=32.
// Dynamic smem: 2 stages x (Ah,Al,Bh,Bl) x 128x40 bf16 = 81920 B.
// ---------------------------------------------------------------------------
#define RS 40
#define TILE_B 10240
#define STAGE_B 40960

__global__ __launch_bounds__(256, 2)
void dual_gemm_bf16(const __nv_bfloat16* __restrict__ A1h,
                    const __nv_bfloat16* __restrict__ A1l,
                    const __nv_bfloat16* __restrict__ A2h,
                    const __nv_bfloat16* __restrict__ A2l,
                    const __nv_bfloat16* __restrict__ B1h,
                    const __nv_bfloat16* __restrict__ B1l,
                    const __nv_bfloat16* __restrict__ B2h,
                    const __nv_bfloat16* __restrict__ B2l,
                    const float* __restrict__ bias, float* __restrict__ C,
                    __nv_bfloat16* __restrict__ Chi,
                    __nv_bfloat16* __restrict__ Clo,
                    int N, int Kpad, int M, int do_relu) {
    extern __shared__ __align__(16) char dynsmem[];
    uint32_t ubase = (uint32_t)__cvta_generic_to_shared(dynsmem);

    int tid = threadIdx.x;
    int lane = tid & 31, wid = tid >> 5;
    int wr = wid & 3, wc = wid >> 2;
    int m0w = wr * 32, n0w = wc * 64;
    int gid = lane >> 2, tig = lane & 3;

    int rowBase = blockIdx.y * 128;
    int colBase = blockIdx.x * 128;

    int a_row = (lane & 7) + ((lane >> 3) & 1) * 8;
    int a_koff = (lane >> 4) * 16;
    int b_row = lane & 7;
    int b_koff = ((lane >> 3) & 1) * 16;

    // per-thread load coords (2 chunk copies per tile per thread)
    int lr0 = tid >> 2, lc0 = tid & 3;           // rows 0..63
    int lr1 = (tid + 256) >> 2, lc1 = tid & 3;   // rows 64..127

    float acc[2][8][4];
    #pragma unroll
    for (int mt = 0; mt < 2; mt++)
        #pragma unroll
        for (int nt = 0; nt < 8; nt++)
            #pragma unroll
            for (int i = 0; i < 4; i++) acc[mt][nt][i] = 0.f;

    const int nch = Kpad >> 5;
    const int npass = (A2h != nullptr) ? 2 : 1;
    const int T = npass * nch;

    // ---- loader ----
    auto load_iter = [&](int it, int stage) {
        int pass = (it >= nch) ? 1 : 0;
        int ch = it - pass * nch;
        int k0 = ch << 5;
        const __nv_bfloat16* AH = pass ? A2h : A1h;
        const __nv_bfloat16* AL = pass ? A2l : A1l;
        const __nv_bfloat16* BH = pass ? B2h : B1h;
        const __nv_bfloat16* BL = pass ? B2l : B1l;
        uint32_t sb = ubase + stage * STAGE_B;
        // A tile
        {
            int gr0 = rowBase + lr0;
            int gr1 = rowBase + lr1;
            int g0 = (gr0 < N) ? gr0 : 0, s0 = (gr0 < N) ? 16 : 0;
            int g1 = (gr1 < N) ? gr1 : 0, s1 = (gr1 < N) ? 16 : 0;
            size_t o0 = (size_t)g0 * Kpad + k0 + lc0 * 8;
            size_t o1 = (size_t)g1 * Kpad + k0 + lc1 * 8;
            cpa16(sb + lr0 * 80 + lc0 * 16, AH + o0, s0);
            cpa16(sb + lr1 * 80 + lc1 * 16, AH + o1, s1);
            cpa16(sb + TILE_B + lr0 * 80 + lc0 * 16, AL + o0, s0);
            cpa16(sb + TILE_B + lr1 * 80 + lc1 * 16, AL + o1, s1);
        }
        // B tile (always in-bounds: weights padded, M multiple of 128)
        {
            size_t o0 = (size_t)(colBase + lr0) * Kpad + k0 + lc0 * 8;
            size_t o1 = (size_t)(colBase + lr1) * Kpad + k0 + lc1 * 8;
            cpa16(sb + 2 * TILE_B + lr0 * 80 + lc0 * 16, BH + o0, 16);
            cpa16(sb + 2 * TILE_B + lr1 * 80 + lc1 * 16, BH + o1, 16);
            cpa16(sb + 3 * TILE_B + lr0 * 80 + lc0 * 16, BL + o0, 16);
            cpa16(sb + 3 * TILE_B + lr1 * 80 + lc1 * 16, BL + o1, 16);
        }
        asm volatile("cp.async.commit_group;" ::: "memory");
    };

    load_iter(0, 0);

    #pragma unroll 1
    for (int it = 0; it < T; ++it) {
        if (it + 1 < T) {
            load_iter(it + 1, (it + 1) & 1);
            asm volatile("cp.async.wait_group 1;" ::: "memory");
        } else {
            asm volatile("cp.async.wait_group 0;" ::: "memory");
        }
        __syncthreads();

        uint32_t sb = ubase + (it & 1) * STAGE_B;
        uint32_t uAh = sb, uAl = sb + TILE_B;
        uint32_t uBh = sb + 2 * TILE_B, uBl = sb + 3 * TILE_B;

        #pragma unroll
        for (int ks = 0; ks < 2; ++ks) {
            int kb = ks * 32;
            unsigned ah[2][4], al[2][4];
            #pragma unroll
            for (int mt = 0; mt < 2; mt++) {
                uint32_t ao = (uint32_t)((m0w + mt * 16 + a_row) * 80
                                         + kb + a_koff);
                ldm_x4(ah[mt], uAh + ao);
                ldm_x4(al[mt], uAl + ao);
            }
            #pragma unroll
            for (int nt = 0; nt < 8; nt++) {
                uint32_t bo = (uint32_t)((n0w + nt * 8 + b_row) * 80
                                         + kb + b_koff);
                unsigned bh[2], bl[2];
                ldm_x2(bh, uBh + bo);
                ldm_x2(bl, uBl + bo);
                #pragma unroll
                for (int mt = 0; mt < 2; mt++) {
                    mma_bf16(acc[mt][nt], ah[mt], bh[0], bh[1]);
                    mma_bf16(acc[mt][nt], al[mt], bh[0], bh[1]);
                    mma_bf16(acc[mt][nt], ah[mt], bl[0], bl[1]);
                }
            }
        }
        __syncthreads();
    }

    // ---- Epilogue ----
    #pragma unroll
    for (int mt = 0; mt < 2; mt++) {
        #pragma unroll
        for (int nt = 0; nt < 8; nt++) {
            int r = rowBase + m0w + mt * 16 + gid;
            int c = colBase + n0w + nt * 8 + tig * 2;
            float b0v = bias[c], b1v = bias[c + 1];
            #pragma unroll
            for (int half = 0; half < 2; ++half) {
                int rr = r + half * 8;
                if (rr >= N) continue;
                float v0 = acc[mt][nt][2 * half + 0] + b0v;
                float v1 = acc[mt][nt][2 * half + 1] + b1v;
                if (do_relu) {
                    v0 = v0 > 0.f ? v0 : 0.f;
                    v1 = v1 > 0.f ? v1 : 0.f;
                }
                size_t o = (size_t)rr * M + c;
                if (C) {
                    C[o] = v0;
                    C[o + 1] = v1;
                }
                if (Chi) {
                    __nv_bfloat162 hh = __floats2bfloat162_rn(v0, v1);
                    __nv_bfloat162 ll = __floats2bfloat162_rn(
                        v0 - __bfloat162float(hh.x), v1 - __bfloat162float(hh.y));
                    *(unsigned*)(Chi + o) = *(unsigned*)&hh;
                    *(unsigned*)(Clo + o) = *(unsigned*)&ll;
                }
            }
        }
    }
}

// ---------------------------------------------------------------------------
// LayerNorm(128) + ReLU + graph pooling over precomputed z = fc(h3).
// ---------------------------------------------------------------------------
#define LN_ROWS 16

__global__ __launch_bounds__(128)
void ln_pool(const float* __restrict__ z, const float* __restrict__ lng,
             const float* __restrict__ lnb, const int* __restrict__ batch,
             float* __restrict__ xa, float* __restrict__ pooled, int N) {
    __shared__ float ws[4], ws2[4];
    int c = threadIdx.x;
    int lane = c & 31;
    int wid = c >> 5;
    int r0 = blockIdx.x * LN_ROWS;
    int nr = min(LN_ROWS, N - r0);

    float g = lng[c], b = lnb[c];
    float pacc = 0.f;
    int curg = -1;
    for (int r = 0; r < nr; ++r) {
        float v = z[(size_t)(r0 + r) * 128 + c];
        float s = v, s2 = v * v;
        #pragma unroll
        for (int o = 16; o > 0; o >>= 1) {
            s  += __shfl_xor_sync(0xffffffffu, s, o);
            s2 += __shfl_xor_sync(0xffffffffu, s2, o);
        }
        __syncthreads();
        if (lane == 0) { ws[wid] = s; ws2[wid] = s2; }
        __syncthreads();
        float sum = ws[0] + ws[1] + ws[2] + ws[3];
        float sum2 = ws2[0] + ws2[1] + ws2[2] + ws2[3];
        float mu = sum * (1.f / 128.f);
        float var = sum2 * (1.f / 128.f) - mu * mu;
        float zz = (v - mu) * rsqrtf(var + 1e-5f) * g + b;
        float relu = zz > 0.f ? zz : 0.f;
        xa[(size_t)(r0 + r) * 128 + c] = relu;

        int gb = batch[r0 + r];
        if (gb != curg) {
            if (curg >= 0) atomicAdd(&pooled[(size_t)curg * 128 + c], pacc);
            curg = gb;
            pacc = 0.f;
        }
        pacc += relu;
    }
    if (curg >= 0) atomicAdd(&pooled[(size_t)curg * 128 + c], pacc);
}

// ---------------------------------------------------------------------------
// Launch
// ---------------------------------------------------------------------------
extern "C" void kernel_launch(void* const* d_in, const int* in_sizes, int n_in,
                              void* d_out, int out_size) {
    const float* x     = (const float*)d_in[0];
    const int*   ei    = (const int*)d_in[1];
    const int*   batch = (const int*)d_in[2];
    const float* W1r = (const float*)d_in[3];
    const float* b1  = (const float*)d_in[4];
    const float* W1o = (const float*)d_in[5];
    const float* W2r = (const float*)d_in[6];
    const float* b2  = (const float*)d_in[7];
    const float* W2o = (const float*)d_in[8];
    const float* W3r = (const float*)d_in[9];
    const float* b3  = (const float*)d_in[10];
    const float* W3o = (const float*)d_in[11];
    const float* Wfc = (const float*)d_in[12];
    const float* bfc = (const float*)d_in[13];
    const float* lng = (const float*)d_in[14];
    const float* lnb = (const float*)d_in[15];

    float* out = (float*)d_out;
    float* x_atom = out;
    float* pooled = out + (size_t)N_NODES * 128;

    float *h1, *h2;
    __nv_bfloat16 *aggh, *aggl, *bAh, *bAl, *bBh, *bBl, *wth, *wtl;
    cudaGetSymbolAddress((void**)&h1, g_h1);
    cudaGetSymbolAddress((void**)&h2, g_h2);
    cudaGetSymbolAddress((void**)&aggh, g_agg_hi);
    cudaGetSymbolAddress((void**)&aggl, g_agg_lo);
    cudaGetSymbolAddress((void**)&bAh, g_bufA_hi);
    cudaGetSymbolAddress((void**)&bAl, g_bufA_lo);
    cudaGetSymbolAddress((void**)&bBh, g_bufB_hi);
    cudaGetSymbolAddress((void**)&bBl, g_bufB_lo);
    cudaGetSymbolAddress((void**)&wth, g_wt_hi);
    cudaGetSymbolAddress((void**)&wtl, g_wt_lo);

    cudaFuncSetAttribute(dual_gemm_bf16,
                         cudaFuncAttributeMaxDynamicSharedMemorySize, 81920);

    const int gridY = (N_NODES + 127) / 128;
    const int gatherBlocks = (N_NODES * 32 + 255) / 256;

    // ---- Weight prep ----
    prep_wt<<<(256 * 96 + 255) / 256, 256>>>(W1r, wth + 0,      wtl + 0,      78, 256, 96);
    prep_wt<<<(256 * 96 + 255) / 256, 256>>>(W1o, wth + 24576,  wtl + 24576,  78, 256, 96);
    prep_wt<<<(512 * 256 + 255) / 256, 256>>>(W2r, wth + 49152,  wtl + 49152,  256, 512, 256);
    prep_wt<<<(512 * 256 + 255) / 256, 256>>>(W2o, wth + 180224, wtl + 180224, 256, 512, 256);
    prep_wt<<<(512 * 512 + 255) / 256, 256>>>(W3r, wth + 311296, wtl + 311296, 512, 512, 512);
    prep_wt<<<(512 * 512 + 255) / 256, 256>>>(W3o, wth + 573440, wtl + 573440, 512, 512, 512);
    prep_wt<<<(128 * 512 + 255) / 256, 256>>>(Wfc, wth + 835584, wtl + 835584, 512, 128, 512);
    prep_x<<<(N_NODES * 96 + 255) / 256, 256>>>(x, bAh, bAl);

    // ---- CSR build ----
    {
        int* pcnt; cudaGetSymbolAddress((void**)&pcnt, g_cnt);
        zero_int<<<(N_NODES + 255) / 256, 256>>>(pcnt, N_NODES);
    }
    hist_kernel<<<(N_EDGES + 255) / 256, 256>>>(ei);
    scan1<<<(N_NODES + 1023) / 1024, 1024>>>();
    scan2<<<1, 32>>>((N_NODES + 1023) / 1024);
    scan3<<<(N_NODES + 255) / 256, 256>>>();
    fill_kernel<<<(N_EDGES + 255) / 256, 256>>>(ei);

    // ---- Layer 1: 78 -> 256 ----
    gather78<<<gatherBlocks, 256>>>(x, aggh, aggl);
    {
        dim3 grid(2, gridY);
        dual_gemm_bf16<<<grid, 256, 81920>>>(aggh, aggl, bAh, bAl,
                                             wth + 0, wtl + 0,
                                             wth + 24576, wtl + 24576,
                                             b1, h1, bBh, bBl,
                                             N_NODES, 96, 256, 1);
    }

    // ---- Layer 2: 256 -> 512 ----
    gather_vec4<<<gatherBlocks, 256>>>(h1, 256, aggh, aggl);
    {
        dim3 grid(4, gridY);
        dual_gemm_bf16<<<grid, 256, 81920>>>(aggh, aggl, bBh, bBl,
                                             wth + 49152, wtl + 49152,
                                             wth + 180224, wtl + 180224,
                                             b2, h2, bAh, bAl,
                                             N_NODES, 256, 512, 1);
    }

    // ---- Layer 3: 512 -> 512 (no fp32 out; bf16 hi/lo feeds FC) ----
    gather_vec4<<<gatherBlocks, 256>>>(h2, 512, aggh, aggl);
    {
        dim3 grid(4, gridY);
        dual_gemm_bf16<<<grid, 256, 81920>>>(aggh, aggl, bAh, bAl,
                                             wth + 311296, wtl + 311296,
                                             wth + 573440, wtl + 573440,
                                             b3, (float*)nullptr, bBh, bBl,
                                             N_NODES, 512, 512, 1);
    }

    // ---- FC 512->128 via GEMM (no relu), then LN + ReLU + pool ----
    {
        dim3 grid(1, gridY);
        dual_gemm_bf16<<<grid, 256, 81920>>>(bBh, bBl,
                                             (__nv_bfloat16*)nullptr,
                                             (__nv_bfloat16*)nullptr,
                                             wth + 835584, wtl + 835584,
                                             (__nv_bfloat16*)nullptr,
                                             (__nv_bfloat16*)nullptr,
                                             bfc, h1,
                                             (__nv_bfloat16*)nullptr,
                                             (__nv_bfloat16*)nullptr,
                                             N_NODES, 512, 128, 0);
    }
    zero_kernel<<<128, 256>>>((float4*)pooled, N_GRAPHS * 128 / 4);
    ln_pool<<<(N_NODES + LN_ROWS - 1) / LN_ROWS, 128>>>(
        h1, lng, lnb, batch, x_atom, pooled, N_NODES);
}